// round 9
// baseline (speedup 1.0000x reference)
#include <cuda_runtime.h>
#include <cstdint>
#include <cstddef>

#define N_NODES 100000
#define N_EDGES 1600000
#define F_IN    128
#define F_HID   128
#define F_OUT   64

typedef unsigned long long ull;

#define SCB 1024
#define NSCB ((N_NODES + SCB - 1) / SCB)

// ---------------------------------------------------------------------------
// Scratch (device globals)
// ---------------------------------------------------------------------------
__device__ int   g_cnt     [N_NODES];
__device__ int   g_rowstart[N_NODES + 1];
__device__ int   g_cursor  [N_NODES];
__device__ int   g_csr     [N_EDGES];
__device__ int   g_bsum    [NSCB];
__device__ int   g_boff    [NSCB];
__device__ int   g_total;
__device__ float g_dinv    [N_NODES];
__device__ float g_h1 [(size_t)N_NODES * F_HID];   // x @ W1 (UNSCALED)
__device__ float g_h2 [(size_t)N_NODES * F_OUT];   // dinv * (y1 @ W2)

// ---------------------------------------------------------------------------
// Packed fp32x2 helpers (sm_100+)
// ---------------------------------------------------------------------------
__device__ __forceinline__ void ffma2(ull& d, ull a, ull b) {
    asm("fma.rn.f32x2 %0, %1, %2, %0;" : "+l"(d) : "l"(a), "l"(b));
}
__device__ __forceinline__ ull pack2(float x) {
    ull r; asm("mov.b64 %0, {%1, %1};" : "=l"(r) : "f"(x)); return r;
}
__device__ __forceinline__ float2 unpack2(ull v) {
    float2 r; asm("mov.b64 {%0, %1}, %2;" : "=f"(r.x), "=f"(r.y) : "l"(v)); return r;
}

// ---------------------------------------------------------------------------
// CSR build: histogram -> 3-phase scan -> cursor placement
// ---------------------------------------------------------------------------
__global__ void zero_cnt_kernel(int n) {
    int i = blockIdx.x * blockDim.x + threadIdx.x;
    if (i < n) g_cnt[i] = 0;
}

__global__ void hist_kernel(const int* __restrict__ dst, int E) {
    int e = blockIdx.x * blockDim.x + threadIdx.x;
    if (e < E) atomicAdd(&g_cnt[dst[e]], 1);
}

__global__ void scan_local_kernel(int N) {
    __shared__ int s[SCB];
    const int t = threadIdx.x;
    const int i = blockIdx.x * SCB + t;
    const int v = (i < N) ? g_cnt[i] : 0;
    s[t] = v;
    __syncthreads();
    for (int off = 1; off < SCB; off <<= 1) {
        int u = (t >= off) ? s[t - off] : 0;
        __syncthreads();
        s[t] += u;
        __syncthreads();
    }
    const int incl = s[t];
    if (i < N) g_rowstart[i] = incl - v;
    if (t == SCB - 1) g_bsum[blockIdx.x] = incl;
}

__global__ void scan_block_kernel(int nb) {
    __shared__ int s[SCB];
    const int t = threadIdx.x;
    const int v = (t < nb) ? g_bsum[t] : 0;
    s[t] = v;
    __syncthreads();
    for (int off = 1; off < SCB; off <<= 1) {
        int u = (t >= off) ? s[t - off] : 0;
        __syncthreads();
        s[t] += u;
        __syncthreads();
    }
    if (t < nb) g_boff[t] = s[t] - v;
    if (t == nb - 1) g_total = s[t];
}

__global__ void scan_fix_kernel(int N) {
    const int i = blockIdx.x * blockDim.x + threadIdx.x;
    if (i < N) {
        const int rs = g_rowstart[i] + g_boff[i >> 10];
        g_rowstart[i] = rs;
        g_cursor[i]   = rs;
        g_dinv[i]     = rsqrtf((float)g_cnt[i] + 1.0f);
    }
    if (i == 0) g_rowstart[N] = g_total;
}

__global__ void place_kernel(const int* __restrict__ src,
                             const int* __restrict__ dst, int E) {
    int e = blockIdx.x * blockDim.x + threadIdx.x;
    if (e < E) {
        int d = dst[e];
        int p = atomicAdd(&g_cursor[d], 1);
        g_csr[p] = src[e];
    }
}

// ---------------------------------------------------------------------------
// GEMM1 (unscaled), packed fp32x2, transposed-x staging.
// ---------------------------------------------------------------------------
#define KCHUNK 64

__global__ __launch_bounds__(256, 2)
void gemm1_kernel(const float* __restrict__ X,
                  const float* __restrict__ W,
                  float* __restrict__ out,
                  int nrows)
{
    constexpr int NOUT = 128;
    constexpr int TXN = NOUT / 8;      // 16
    constexpr int TYN = 256 / TXN;     // 16
    constexpr int TM  = 128 / TYN;     // 8

    extern __shared__ float sm[];
    float* ws = sm;                    // [128][128]
    float* xs = sm + 128 * NOUT;       // [KCHUNK][128] k-major

    const int row0 = blockIdx.x * 128;
    const int tid  = threadIdx.x;
    const int tx   = tid % TXN;
    const int ty   = tid / TXN;

    {
        const float4* Wv = (const float4*)W;
        float4* wsv = (float4*)ws;
        for (int i = tid; i < 128 * NOUT / 4; i += 256) wsv[i] = Wv[i];
    }

    ull acc[TM][4];
#pragma unroll
    for (int i = 0; i < TM; i++)
#pragma unroll
        for (int j = 0; j < 4; j++) acc[i][j] = 0ull;

    for (int kc = 0; kc < 128; kc += KCHUNK) {
        __syncthreads();
        for (int i = tid; i < (KCHUNK / 4) * 128; i += 256) {
            const int q = i >> 7;
            const int r = i & 127;
            float4 v = make_float4(0.f, 0.f, 0.f, 0.f);
            const int gr = row0 + r;
            if (gr < nrows) v = ((const float4*)X)[(size_t)gr * 32 + (kc >> 2) + q];
            xs[(q * 4 + 0) * 128 + r] = v.x;
            xs[(q * 4 + 1) * 128 + r] = v.y;
            xs[(q * 4 + 2) * 128 + r] = v.z;
            xs[(q * 4 + 3) * 128 + r] = v.w;
        }
        __syncthreads();

#pragma unroll 8
        for (int k = 0; k < KCHUNK; k++) {
            const ulonglong2 wv0 = *(const ulonglong2*)(ws + (size_t)(kc + k) * NOUT + tx * 8);
            const ulonglong2 wv1 = *(const ulonglong2*)(ws + (size_t)(kc + k) * NOUT + tx * 8 + 4);
            const float* xr = xs + k * 128 + ty * TM;
            const float4 xa = *(const float4*)xr;
            const float4 xb = *(const float4*)(xr + 4);
            const float xv[8] = {xa.x, xa.y, xa.z, xa.w, xb.x, xb.y, xb.z, xb.w};
#pragma unroll
            for (int i = 0; i < 8; i++) {
                const ull xx = pack2(xv[i]);
                ffma2(acc[i][0], xx, wv0.x);
                ffma2(acc[i][1], xx, wv0.y);
                ffma2(acc[i][2], xx, wv1.x);
                ffma2(acc[i][3], xx, wv1.y);
            }
        }
    }

#pragma unroll
    for (int i = 0; i < TM; i++) {
        const int r = row0 + ty * TM + i;
        if (r < nrows) {
            const float2 p0 = unpack2(acc[i][0]);
            const float2 p1 = unpack2(acc[i][1]);
            const float2 p2 = unpack2(acc[i][2]);
            const float2 p3 = unpack2(acc[i][3]);
            float4 o0 = {p0.x, p0.y, p1.x, p1.y};
            float4 o1 = {p2.x, p2.y, p3.x, p3.y};
            const size_t base = (size_t)r * NOUT + tx * 8;
            *(float4*)(out + base)     = o0;
            *(float4*)(out + base + 4) = o1;
        }
    }
}

// ---------------------------------------------------------------------------
// FUSED: layer-1 aggregation (+dinv+bias+ReLU) into smem tile, then GEMM2.
//   Phase A (per 128-node tile): ys[r][:] = relu(dinv[n]*(dinv[n]*h1[n] +
//                                  sum_e dinv[s]*h1[s]) + b1)    (row-major smem)
//   Phase B: h2[r][:] = dinv[r] * (ys[r][:] @ W2)
// smem: ws2 [128][64] = 32KB,  ys [128][132] = 66KB  -> 98KB, 2 CTAs/SM.
// ---------------------------------------------------------------------------
#define YP 132   // ys pitch (floats)

__global__ __launch_bounds__(256, 2)
void fused_agg_gemm2_kernel(const float4* __restrict__ h,   // g_h1 as [N][32]
                            const float*  __restrict__ b1,
                            const float*  __restrict__ W2,   // [128][64]
                            float* __restrict__ out,         // g_h2 [N][64]
                            int N)
{
    extern __shared__ float sm[];
    float* ws = sm;              // [128][64]
    float* ys = sm + 128 * 64;   // [128][YP]

    const int row0 = blockIdx.x * 128;
    const int tid  = threadIdx.x;
    const int wid  = tid >> 5;
    const int lane = tid & 31;

    // Load W2 into smem (streamed, overlaps phase A issue)
    {
        const float4* Wv = (const float4*)W2;
        float4* wsv = (float4*)ws;
        for (int i = tid; i < 128 * 64 / 4; i += 256) wsv[i] = Wv[i];
    }

    // ---- Phase A: 8 warps x 16 nodes each ----
    const float4 bb = ((const float4*)b1)[lane];
#pragma unroll 1
    for (int i = 0; i < 16; i++) {
        const int r = wid * 16 + i;
        const int n = row0 + r;
        float4 o = make_float4(0.f, 0.f, 0.f, 0.f);
        if (n < N) {
            const float dvn = __ldg(g_dinv + n);
            const float4 hs = h[(size_t)n * 32 + lane];
            float4 acc;
            acc.x = hs.x * dvn; acc.y = hs.y * dvn;
            acc.z = hs.z * dvn; acc.w = hs.w * dvn;

            const int start = g_rowstart[n];
            const int end   = g_rowstart[n + 1];
            int e = start;
            for (; e + 4 <= end; e += 4) {
                const int s0 = __ldg(g_csr + e);
                const int s1 = __ldg(g_csr + e + 1);
                const int s2 = __ldg(g_csr + e + 2);
                const int s3 = __ldg(g_csr + e + 3);
                const float d0 = __ldg(g_dinv + s0);
                const float d1 = __ldg(g_dinv + s1);
                const float d2 = __ldg(g_dinv + s2);
                const float d3 = __ldg(g_dinv + s3);
                const float4 v0 = h[(size_t)s0 * 32 + lane];
                const float4 v1 = h[(size_t)s1 * 32 + lane];
                const float4 v2 = h[(size_t)s2 * 32 + lane];
                const float4 v3 = h[(size_t)s3 * 32 + lane];
                acc.x += v0.x * d0 + v1.x * d1 + v2.x * d2 + v3.x * d3;
                acc.y += v0.y * d0 + v1.y * d1 + v2.y * d2 + v3.y * d3;
                acc.z += v0.z * d0 + v1.z * d1 + v2.z * d2 + v3.z * d3;
                acc.w += v0.w * d0 + v1.w * d1 + v2.w * d2 + v3.w * d3;
            }
            for (; e < end; e++) {
                const int s = __ldg(g_csr + e);
                const float d = __ldg(g_dinv + s);
                const float4 v = h[(size_t)s * 32 + lane];
                acc.x += v.x * d; acc.y += v.y * d;
                acc.z += v.z * d; acc.w += v.w * d;
            }
            o.x = fmaxf(acc.x * dvn + bb.x, 0.f);
            o.y = fmaxf(acc.y * dvn + bb.y, 0.f);
            o.z = fmaxf(acc.z * dvn + bb.z, 0.f);
            o.w = fmaxf(acc.w * dvn + bb.w, 0.f);
        }
        *(float4*)(ys + r * YP + lane * 4) = o;   // conflict-free STS.128
    }
    __syncthreads();

    // ---- Phase B: GEMM ys[128][128] @ ws[128][64], TXN=8, TYN=32, TM=4 ----
    const int tx = tid % 8;
    const int ty = tid / 8;

    ull acc[4][4];
#pragma unroll
    for (int i = 0; i < 4; i++)
#pragma unroll
        for (int j = 0; j < 4; j++) acc[i][j] = 0ull;

#pragma unroll 8
    for (int k = 0; k < 128; k++) {
        const ulonglong2 wv0 = *(const ulonglong2*)(ws + k * 64 + tx * 8);
        const ulonglong2 wv1 = *(const ulonglong2*)(ws + k * 64 + tx * 8 + 4);
#pragma unroll
        for (int i = 0; i < 4; i++) {
            const ull xx = pack2(ys[(ty * 4 + i) * YP + k]);  // 4-addr broadcast
            ffma2(acc[i][0], xx, wv0.x);
            ffma2(acc[i][1], xx, wv0.y);
            ffma2(acc[i][2], xx, wv1.x);
            ffma2(acc[i][3], xx, wv1.y);
        }
    }

#pragma unroll
    for (int i = 0; i < 4; i++) {
        const int r = row0 + ty * 4 + i;
        if (r < N) {
            const float dv = g_dinv[r];
            const float2 p0 = unpack2(acc[i][0]);
            const float2 p1 = unpack2(acc[i][1]);
            const float2 p2 = unpack2(acc[i][2]);
            const float2 p3 = unpack2(acc[i][3]);
            float4 o0, o1;
            o0.x = p0.x * dv; o0.y = p0.y * dv;
            o0.z = p1.x * dv; o0.w = p1.y * dv;
            o1.x = p2.x * dv; o1.y = p2.y * dv;
            o1.z = p3.x * dv; o1.w = p3.y * dv;
            const size_t base = (size_t)r * 64 + tx * 8;
            *(float4*)(out + base)     = o0;
            *(float4*)(out + base + 4) = o1;
        }
    }
}

// ---------------------------------------------------------------------------
// Layer-2 aggregation: h2 pre-scaled by dinv. 2 nodes/warp, 16 lanes each.
// ---------------------------------------------------------------------------
__global__ __launch_bounds__(256)
void agg64_kernel(const float4* __restrict__ h,   // [N][16]
                  const float*  __restrict__ b,
                  float4* __restrict__ out, int N)
{
    const int pair = (blockIdx.x * blockDim.x + threadIdx.x) >> 5;
    const int half = (threadIdx.x >> 4) & 1;
    const int lane = threadIdx.x & 15;
    const int n = pair * 2 + half;
    if (n >= N) return;

    float4 acc = h[(size_t)n * 16 + lane];  // self-loop
    const int start = g_rowstart[n];
    const int end   = g_rowstart[n + 1];

    int e = start;
    for (; e + 4 <= end; e += 4) {
        const int s0 = __ldg(g_csr + e);
        const int s1 = __ldg(g_csr + e + 1);
        const int s2 = __ldg(g_csr + e + 2);
        const int s3 = __ldg(g_csr + e + 3);
        const float4 v0 = h[(size_t)s0 * 16 + lane];
        const float4 v1 = h[(size_t)s1 * 16 + lane];
        const float4 v2 = h[(size_t)s2 * 16 + lane];
        const float4 v3 = h[(size_t)s3 * 16 + lane];
        acc.x += v0.x + v1.x + v2.x + v3.x;
        acc.y += v0.y + v1.y + v2.y + v3.y;
        acc.z += v0.z + v1.z + v2.z + v3.z;
        acc.w += v0.w + v1.w + v2.w + v3.w;
    }
    for (; e < end; e++) {
        const int s = __ldg(g_csr + e);
        const float4 v = h[(size_t)s * 16 + lane];
        acc.x += v.x; acc.y += v.y; acc.z += v.z; acc.w += v.w;
    }

    const float dv = g_dinv[n];
    const float4 bb = ((const float4*)b)[lane];
    float4 o;
    o.x = acc.x * dv + bb.x;
    o.y = acc.y * dv + bb.y;
    o.z = acc.z * dv + bb.z;
    o.w = acc.w * dv + bb.w;
    out[(size_t)n * 16 + lane] = o;
}

// ---------------------------------------------------------------------------
// Launch: CSR build on aux stream, GEMM1 on main stream, event fork/join.
// ---------------------------------------------------------------------------
extern "C" void kernel_launch(void* const* d_in, const int* in_sizes, int n_in,
                              void* d_out, int out_size)
{
    const float* x  = (const float*)d_in[0];
    const int*   ei = (const int*)  d_in[1];
    const float* W1 = (const float*)d_in[2];
    const float* b1 = (const float*)d_in[3];
    const float* W2 = (const float*)d_in[4];
    const float* b2 = (const float*)d_in[5];
    float* out = (float*)d_out;

    const int N = in_sizes[0] / F_IN;
    const int E = in_sizes[1] / 2;
    const int* src = ei;
    const int* dst = ei + E;

    float *p_h1, *p_h2;
    cudaGetSymbolAddress((void**)&p_h1, g_h1);
    cudaGetSymbolAddress((void**)&p_h2, g_h2);

    const int smem1 = (128 * F_HID + KCHUNK * 128) * (int)sizeof(float);   // 96 KB
    const int smemF = (128 * F_OUT + 128 * YP) * (int)sizeof(float);       // 98 KB
    cudaFuncSetAttribute(gemm1_kernel,
                         cudaFuncAttributeMaxDynamicSharedMemorySize, smem1);
    cudaFuncSetAttribute(fused_agg_gemm2_kernel,
                         cudaFuncAttributeMaxDynamicSharedMemorySize, smemF);

    // One-time resources (created on the uncaptured correctness call)
    static cudaStream_t s_aux = nullptr;
    static cudaEvent_t  ev_fork = nullptr, ev_join = nullptr;
    if (s_aux == nullptr) {
        cudaStreamCreateWithFlags(&s_aux, cudaStreamNonBlocking);
        cudaEventCreateWithFlags(&ev_fork, cudaEventDisableTiming);
        cudaEventCreateWithFlags(&ev_join, cudaEventDisableTiming);
    }

    const int T = 256;
    const int nscb = (N + SCB - 1) / SCB;
    const int gblk = (N + 127) / 128;

    // Fork: CSR build on s_aux, GEMM1 on main stream, concurrently.
    cudaEventRecord(ev_fork, 0);
    cudaStreamWaitEvent(s_aux, ev_fork, 0);

    zero_cnt_kernel  <<<(N + T - 1) / T, T, 0, s_aux>>>(N);
    hist_kernel      <<<(E + T - 1) / T, T, 0, s_aux>>>(dst, E);
    scan_local_kernel<<<nscb, SCB, 0, s_aux>>>(N);
    scan_block_kernel<<<1, SCB, 0, s_aux>>>(nscb);
    scan_fix_kernel  <<<(N + T - 1) / T, T, 0, s_aux>>>(N);
    place_kernel     <<<(E + T - 1) / T, T, 0, s_aux>>>(src, dst, E);
    cudaEventRecord(ev_join, s_aux);

    gemm1_kernel<<<gblk, T, smem1>>>(x, W1, p_h1, N);  // main stream

    // Join
    cudaStreamWaitEvent(0, ev_join, 0);

    // Fused agg1+ReLU+GEMM2, then agg2
    fused_agg_gemm2_kernel<<<gblk, T, smemF>>>((const float4*)p_h1, b1, W2, p_h2, N);
    {
        const int pairs = (N + 1) / 2;
        const int blocks = (pairs * 32 + T - 1) / T;
        agg64_kernel<<<blocks, T>>>((const float4*)p_h2, b2, (float4*)out, N);
    }
}